// round 1
// baseline (speedup 1.0000x reference)
#include <cuda_runtime.h>
#include <cuda_bf16.h>
#include <math.h>

// Problem constants (fixed by the dataset's setup_inputs)
#define NRHO   32
#define NXP    480            // rows (y_phi length)
#define NYP    240            // cols before mirror (x_phi length)
#define NFULL  480            // mirrored width
#define INV2S2 512.0          // 1/(2*sigma^2), sigma = 1/32
#define GS     (1.0/480.0)    // grid_size
#define PID    (3.14159265358979323846/1.3)
#define BETA   1.0

// ---- device scratch (no allocations allowed) ----
__device__ double g_A  [NXP * NRHO];     // A[i][a] = exp(-(y_phi[i]-y_rho[a])^2/(2s^2))
__device__ double g_B  [NYP * NRHO];     // B[j][b]
__device__ double g_W  [NYP * NRHO];     // W[j][a] = sum_b M[a][b]*B[j][b]  (transposed layout)
__device__ double g_phi[NXP * NYP];      // phi before mirror
__device__ double g_gx [NXP * NFULL];    // phi_x (+1e-12)
__device__ double g_gy [NXP * NFULL];    // phi_y (+1e-12)
__device__ double g_part[1024];          // block partial sums

// --------------------------------------------------------------------------
// Kernel 1 (single block, 1024 threads):
//   - build K1 (32x32 1-D Gaussian), Gauss-Jordan inverse in fp64
//   - M = K1inv * P * K1inv   (Kronecker solve of the 1024x1024 system)
//   - build B factors, W = M*B^T (stored transposed), and A factors
// --------------------------------------------------------------------------
__global__ void k_solve(const float* __restrict__ params,
                        const float* __restrict__ x_rho,
                        const float* __restrict__ y_rho,
                        const float* __restrict__ x_phi,
                        const float* __restrict__ y_phi)
{
    __shared__ double A[NRHO][NRHO];
    __shared__ double Inv[NRHO][NRHO];
    __shared__ double P[NRHO][NRHO];
    __shared__ double T[NRHO][NRHO];

    const int tid = threadIdx.x;      // 0..1023
    const int r = tid >> 5;
    const int c = tid & 31;

    // K1 from y_rho (== x_rho in this problem)
    {
        double dr = (double)y_rho[r] - (double)y_rho[c];
        A[r][c]   = exp(-dr * dr * INV2S2);
        Inv[r][c] = (r == c) ? 1.0 : 0.0;
        P[r][c]   = (double)params[r * NRHO + c];
    }
    __syncthreads();

    // Gauss-Jordan (no pivoting; K1 is SPD, fp64)
    for (int k = 0; k < NRHO; ++k) {
        double piv = A[k][k];
        __syncthreads();
        if (r == k) {
            double ip = 1.0 / piv;
            A[k][c]   *= ip;
            Inv[k][c] *= ip;
        }
        __syncthreads();
        double f = A[r][k];
        __syncthreads();
        if (r != k) {
            A[r][c]   -= f * A[k][c];
            Inv[r][c] -= f * Inv[k][c];
        }
        __syncthreads();
    }

    // T = Inv * P
    {
        double s = 0.0;
        #pragma unroll
        for (int j = 0; j < NRHO; ++j) s += Inv[r][j] * P[j][c];
        T[r][c] = s;
    }
    __syncthreads();
    // M = T * Inv  (store into P)
    {
        double s = 0.0;
        #pragma unroll
        for (int j = 0; j < NRHO; ++j) s += T[r][j] * Inv[j][c];
        P[r][c] = s;   // P now holds M[a][b]
    }
    __syncthreads();

    // B factors -> global
    for (int idx = tid; idx < NYP * NRHO; idx += blockDim.x) {
        int j = idx >> 5, b = idx & 31;
        double d = (double)x_phi[j] - (double)x_rho[b];
        g_B[idx] = exp(-d * d * INV2S2);
    }
    __syncthreads();

    // W[j][a] = sum_b M[a][b] * B[j][b]
    for (int idx = tid; idx < NYP * NRHO; idx += blockDim.x) {
        int j = idx >> 5, a = idx & 31;
        const double* Brow = g_B + j * NRHO;
        double s = 0.0;
        #pragma unroll
        for (int b = 0; b < NRHO; ++b) s += P[a][b] * Brow[b];
        g_W[idx] = s;
    }

    // A factors -> global
    for (int idx = tid; idx < NXP * NRHO; idx += blockDim.x) {
        int i = idx >> 5, a = idx & 31;
        double d = (double)y_phi[i] - (double)y_rho[a];
        g_A[idx] = exp(-d * d * INV2S2);
    }
}

// --------------------------------------------------------------------------
// Kernel 2: phi[i][j] = sum_a A[i][a] * W[j][a]      (480 x 240)
// --------------------------------------------------------------------------
__global__ void k_phi()
{
    int idx = blockIdx.x * blockDim.x + threadIdx.x;
    if (idx >= NXP * NYP) return;
    int i = idx / NYP, j = idx - i * NYP;
    const double* Ar = g_A + i * NRHO;
    const double* Wc = g_W + j * NRHO;
    double s = 0.0;
    #pragma unroll
    for (int a = 0; a < NRHO; ++a) s += Ar[a] * Wc[a];
    g_phi[idx] = s;
}

// mirrored phi accessor
__device__ __forceinline__ double phi_at(int i, int j)
{
    int js = (j < NYP) ? j : (NFULL - 1 - j);
    return g_phi[i * NYP + js];
}

// --------------------------------------------------------------------------
// Kernel 3: first derivatives on the mirrored 480x480 grid (+1e-12, as ref)
// --------------------------------------------------------------------------
__global__ void k_grad()
{
    int idx = blockIdx.x * blockDim.x + threadIdx.x;
    if (idx >= NXP * NFULL) return;
    int i = idx / NFULL, j = idx - i * NFULL;
    const double d = GS;

    double gx;
    if (i == 0)              gx = (phi_at(1, j) - phi_at(0, j)) / d;
    else if (i == NXP - 1)   gx = (phi_at(NXP - 1, j) - phi_at(NXP - 2, j)) / d;
    else                     gx = (phi_at(i + 1, j) - phi_at(i - 1, j)) / (2.0 * d);

    double gy;
    if (j == 0)              gy = (phi_at(i, 1) - phi_at(i, 0)) / d;
    else if (j == NFULL - 1) gy = (phi_at(i, NFULL - 1) - phi_at(i, NFULL - 2)) / d;
    else                     gy = (phi_at(i, j + 1) - phi_at(i, j - 1)) / (2.0 * d);

    g_gx[idx] = gx + 1e-12;
    g_gy[idx] = gy + 1e-12;
}

// --------------------------------------------------------------------------
// Kernel 4: second derivatives + penalty + deterministic block reduction
// --------------------------------------------------------------------------
__global__ void k_pen()
{
    __shared__ double sh[256];
    int idx = blockIdx.x * blockDim.x + threadIdx.x;
    double pen = 0.0;

    if (idx < NXP * NFULL) {
        int i = idx / NFULL, j = idx - i * NFULL;
        const int row = i * NFULL;
        const double d = GS;

        double px = g_gx[idx];
        double py = g_gy[idx];

        double xx;
        if (i == 0)             xx = (g_gx[NFULL + j] - g_gx[j]) / d;
        else if (i == NXP - 1)  xx = (g_gx[(NXP - 1) * NFULL + j] - g_gx[(NXP - 2) * NFULL + j]) / d;
        else                    xx = (g_gx[(i + 1) * NFULL + j] - g_gx[(i - 1) * NFULL + j]) / (2.0 * d);

        double xy;
        if (j == 0)             xy = (g_gx[row + 1] - g_gx[row]) / d;
        else if (j == NFULL - 1)xy = (g_gx[row + NFULL - 1] - g_gx[row + NFULL - 2]) / d;
        else                    xy = (g_gx[row + j + 1] - g_gx[row + j - 1]) / (2.0 * d);

        double yy;
        if (j == 0)             yy = (g_gy[row + 1] - g_gy[row]) / d;
        else if (j == NFULL - 1)yy = (g_gy[row + NFULL - 1] - g_gy[row + NFULL - 2]) / d;
        else                    yy = (g_gy[row + j + 1] - g_gy[row + j - 1]) / (2.0 * d);

        double p   = phi_at(i, j);
        double pv  = fmax(sqrt(px * px + py * py), 1e-8);
        double pvv = (px * px * xx + 2.0 * px * py * xy + py * py * yy) / (pv * pv);
        pen = fmax(fabs(pvv) / (PID * fabs(p) + BETA * pv) - PID, 0.0);
        if (!(pen == pen)) pen = 0.0;   // nansum semantics
    }

    // deterministic in-block tree reduction
    int t = threadIdx.x;
    sh[t] = pen;
    __syncthreads();
    for (int s = 128; s > 0; s >>= 1) {
        if (t < s) sh[t] += sh[t + s];
        __syncthreads();
    }
    if (t == 0) g_part[blockIdx.x] = sh[0];
}

// --------------------------------------------------------------------------
// Kernel 5: final deterministic reduction of 900 partials, scale, write out
// --------------------------------------------------------------------------
__global__ void k_final(float* __restrict__ out, int npart)
{
    __shared__ double sh[256];
    int t = threadIdx.x;
    double s = 0.0;
    for (int k = t; k < npart; k += 256) s += g_part[k];
    sh[t] = s;
    __syncthreads();
    for (int st = 128; st > 0; st >>= 1) {
        if (t < st) sh[t] += sh[t + st];
        __syncthreads();
    }
    if (t == 0) out[0] = (float)(sh[0] * GS * GS);
}

// --------------------------------------------------------------------------
extern "C" void kernel_launch(void* const* d_in, const int* in_sizes, int n_in,
                              void* d_out, int out_size)
{
    const float* params = (const float*)d_in[0];
    const float* x_rho  = (const float*)d_in[1];
    const float* y_rho  = (const float*)d_in[2];
    const float* x_phi  = (const float*)d_in[3];
    const float* y_phi  = (const float*)d_in[4];
    float* out = (float*)d_out;

    const int nphi  = NXP * NYP;          // 115200
    const int nfull = NXP * NFULL;        // 230400
    const int pen_blocks = (nfull + 255) / 256;   // 900

    k_solve<<<1, 1024>>>(params, x_rho, y_rho, x_phi, y_phi);
    k_phi  <<<(nphi + 127) / 128, 128>>>();
    k_grad <<<(nfull + 255) / 256, 256>>>();
    k_pen  <<<pen_blocks, 256>>>();
    k_final<<<1, 256>>>(out, pen_blocks);
}